// round 5
// baseline (speedup 1.0000x reference)
#include <cuda_runtime.h>
#include <cstdint>

#define BIGF 100000000.0f
// 1/(gamma*ln2) with gamma = 0.1, and gamma*ln2
#define INV_G_LN2 14.426950408889634f
#define G_LN2 0.06931471805599453f

// Fast MUFU-path base-2 exp/log (inline PTX; avoids host/device intrinsic
// naming issues and guarantees MUFU.EX2 / MUFU.LG2 regardless of -use_fast_math).
__device__ __forceinline__ float fast_ex2(float x) {
    float y; asm("ex2.approx.ftz.f32 %0, %1;" : "=f"(y) : "f"(x)); return y;
}
__device__ __forceinline__ float fast_lg2(float x) {
    float y; asm("lg2.approx.ftz.f32 %0, %1;" : "=f"(y) : "f"(x)); return y;
}

// Scratch (static device allocations; no cudaMalloc anywhere)
__device__ float g_D[50331648];  // 192 * 512 * 512 floats = 201 MB
__device__ float g_xn[32768];    // 64*512 row norms of x
__device__ float g_yn[32768];    // 64*512 row norms of y
__device__ float g_dtw[192];     // per-(matrix,batch) soft-DTW values

// ---------------------------------------------------------------------------
// Kernel 1: row squared-norms, one warp per row, both tensors at once.
// ---------------------------------------------------------------------------
__global__ void norms_kernel(const float* __restrict__ x, const float* __restrict__ y) {
    int gw = (blockIdx.x * blockDim.x + threadIdx.x) >> 5;   // global warp id = row
    int lane = threadIdx.x & 31;
    if (gw >= 32768) return;
    const float* p = x + (size_t)gw * 256;
    const float* q = y + (size_t)gw * 256;
    float vx = 0.f, vy = 0.f;
#pragma unroll
    for (int u = 0; u < 8; ++u) {
        float a = p[lane + 32 * u]; vx += a * a;
        float b = q[lane + 32 * u]; vy += b * b;
    }
#pragma unroll
    for (int o = 16; o; o >>= 1) {
        vx += __shfl_xor_sync(0xffffffffu, vx, o);
        vy += __shfl_xor_sync(0xffffffffu, vy, o);
    }
    if (lane == 0) { g_xn[gw] = vx; g_yn[gw] = vy; }
}

// ---------------------------------------------------------------------------
// Kernel 2: squared-distance matrices.
// D[z][i][j] = |A_i|^2 + |B_j|^2 - 2 A_i.B_j, z = m*64+b,
//   m=0: (x,y)  m=1: (x,x)  m=2: (y,y)
// Classic 128x128 tile SGEMM, BK=8, 256 threads, 8x8 microtile.
// ---------------------------------------------------------------------------
__global__ __launch_bounds__(256, 2) void sqdist_kernel(const float* __restrict__ x,
                                                        const float* __restrict__ y) {
    __shared__ __align__(16) float As[8][132];
    __shared__ __align__(16) float Bs[8][132];

    int z = blockIdx.z;
    int m = z >> 6, b = z & 63;
    const float* A; const float* Bm; const float* an; const float* bn;
    if (m == 0)      { A = x; Bm = y; an = g_xn; bn = g_yn; }
    else if (m == 1) { A = x; Bm = x; an = g_xn; bn = g_xn; }
    else             { A = y; Bm = y; an = g_yn; bn = g_yn; }
    size_t boff = (size_t)b * 512 * 256;
    A += boff; Bm += boff; an += b * 512; bn += b * 512;
    float* C = g_D + (size_t)z * 262144;

    int tid = threadIdx.x;
    int rowBase = blockIdx.y * 128, colBase = blockIdx.x * 128;
    int lrow = tid >> 1;            // 0..127
    int lc4  = (tid & 1) * 4;       // 0 or 4
    const float* Ap = A  + (size_t)(rowBase + lrow) * 256 + lc4;
    const float* Bp = Bm + (size_t)(colBase + lrow) * 256 + lc4;
    int tx = tid & 15, ty = tid >> 4;

    float acc[8][8];
#pragma unroll
    for (int i = 0; i < 8; ++i)
#pragma unroll
        for (int j = 0; j < 8; ++j) acc[i][j] = 0.f;

    for (int kb = 0; kb < 256; kb += 8) {
        float4 av = *(const float4*)(Ap + kb);
        float4 bv = *(const float4*)(Bp + kb);
        As[lc4 + 0][lrow] = av.x; As[lc4 + 1][lrow] = av.y;
        As[lc4 + 2][lrow] = av.z; As[lc4 + 3][lrow] = av.w;
        Bs[lc4 + 0][lrow] = bv.x; Bs[lc4 + 1][lrow] = bv.y;
        Bs[lc4 + 2][lrow] = bv.z; Bs[lc4 + 3][lrow] = bv.w;
        __syncthreads();
#pragma unroll
        for (int kk = 0; kk < 8; ++kk) {
            float a[8], bbv[8];
            float4 t0 = *(const float4*)&As[kk][ty * 8];
            float4 t1 = *(const float4*)&As[kk][ty * 8 + 4];
            a[0] = t0.x; a[1] = t0.y; a[2] = t0.z; a[3] = t0.w;
            a[4] = t1.x; a[5] = t1.y; a[6] = t1.z; a[7] = t1.w;
            float4 u0 = *(const float4*)&Bs[kk][tx * 8];
            float4 u1 = *(const float4*)&Bs[kk][tx * 8 + 4];
            bbv[0] = u0.x; bbv[1] = u0.y; bbv[2] = u0.z; bbv[3] = u0.w;
            bbv[4] = u1.x; bbv[5] = u1.y; bbv[6] = u1.z; bbv[7] = u1.w;
#pragma unroll
            for (int i = 0; i < 8; ++i)
#pragma unroll
                for (int j = 0; j < 8; ++j) acc[i][j] += a[i] * bbv[j];
        }
        __syncthreads();
    }

    // epilogue: D = xn + yn - 2*dot
    float bnv[8];
#pragma unroll
    for (int j = 0; j < 8; ++j) bnv[j] = bn[colBase + tx * 8 + j];
#pragma unroll
    for (int i = 0; i < 8; ++i) {
        int gr = rowBase + ty * 8 + i;
        float xn = an[gr];
        float* Crow = C + (size_t)gr * 512 + colBase + tx * 8;
        float4 o0, o1;
        o0.x = xn + bnv[0] - 2.f * acc[i][0];
        o0.y = xn + bnv[1] - 2.f * acc[i][1];
        o0.z = xn + bnv[2] - 2.f * acc[i][2];
        o0.w = xn + bnv[3] - 2.f * acc[i][3];
        o1.x = xn + bnv[4] - 2.f * acc[i][4];
        o1.y = xn + bnv[5] - 2.f * acc[i][5];
        o1.z = xn + bnv[6] - 2.f * acc[i][6];
        o1.w = xn + bnv[7] - 2.f * acc[i][7];
        *(float4*)Crow       = o0;
        *(float4*)(Crow + 4) = o1;
    }
}

// ---------------------------------------------------------------------------
// Kernel 3: soft-DTW anti-diagonal DP. One CTA (512 threads) per instance.
// Thread t owns row i=t+1. r1 = R[i, k-1-i], r2 = R[i, k-2-i].
// Neighbor values via shfl_up inside warps, smem double-buffered edges across
// warps. D staged into smem in 16-diagonal parallelogram bands (coalesced).
// ---------------------------------------------------------------------------
__global__ __launch_bounds__(512, 2) void dtw_kernel() {
    __shared__ float band[512][17];   // 16 diagonals per row + pad
    __shared__ float e1[2][16];
    __shared__ float e2[2][16];

    int inst = blockIdx.x;
    const float* __restrict__ D = g_D + (size_t)inst * 262144;
    int t = threadIdx.x;
    int lane = t & 31, warp = t >> 5;

    if (t < 16) { e1[0][t] = BIGF; e1[1][t] = BIGF; e2[0][t] = BIGF; e2[1][t] = BIGF; }
    float r1 = BIGF, r2 = BIGF;
    __syncthreads();

    for (int kb = 2; kb <= 1024; kb += 16) {
        // Stage band: band[r][u] = D[r][kb - r - 2 + u]  (u = k - kb)
        {
            int rbase = warp * 32;
#pragma unroll
            for (int it = 0; it < 16; ++it) {
                int row = rbase + it * 2 + (lane >> 4);
                int u = lane & 15;
                int c = kb - row - 2 + u;
                float v = 0.f;
                if ((unsigned)c < 512u) v = __ldg(&D[row * 512 + c]);
                band[row][u] = v;
            }
        }
        __syncthreads();

        int kend = (kb + 16 > 1025) ? 1025 : (kb + 16);
        for (int k = kb; k < kend; ++k) {
            float up1 = __shfl_up_sync(0xffffffffu, r1, 1);  // R[i-1, j]
            float up2 = __shfl_up_sync(0xffffffffu, r2, 1);  // R[i-1, j-1]
            if (lane == 0) {
                if (warp == 0) { up1 = BIGF; up2 = (k == 2) ? 0.f : BIGF; }
                else {
                    int rb = (k + 1) & 1;
                    up1 = e1[rb][warp - 1];
                    up2 = e2[rb][warp - 1];
                }
            }
            int jm1 = k - t - 2;
            bool valid = ((unsigned)jm1 < 512u);
            float d = band[t][k - kb];
            float mn = fminf(fminf(up1, up2), r1);
            float s = fast_ex2((mn - up1) * INV_G_LN2)
                    + fast_ex2((mn - up2) * INV_G_LN2)
                    + fast_ex2((mn - r1)  * INV_G_LN2);
            float sm = mn - G_LN2 * fast_lg2(s);
            r2 = r1;
            r1 = valid ? d + sm : BIGF;
            if (lane == 31) {
                int wb = k & 1;
                e1[wb][warp] = r1;
                e2[wb][warp] = r2;
            }
            __syncthreads();
        }
    }
    if (t == 511) g_dtw[inst] = r1;   // R[512, 512]
}

// ---------------------------------------------------------------------------
// Kernel 4: out[b] = dtw_xy - 0.5*(dtw_xx + dtw_yy)
// ---------------------------------------------------------------------------
__global__ void combine_kernel(float* __restrict__ out) {
    int b = threadIdx.x;
    if (b < 64) out[b] = g_dtw[b] - 0.5f * (g_dtw[64 + b] + g_dtw[128 + b]);
}

extern "C" void kernel_launch(void* const* d_in, const int* in_sizes, int n_in,
                              void* d_out, int out_size) {
    const float* x = (const float*)d_in[0];
    const float* y = (const float*)d_in[1];
    float* out = (float*)d_out;

    norms_kernel<<<4096, 256>>>(x, y);
    dim3 g(4, 4, 192);
    sqdist_kernel<<<g, 256>>>(x, y);
    dtw_kernel<<<192, 512>>>();
    combine_kernel<<<1, 64>>>(out);
}

// round 9
// speedup vs baseline: 1.5515x; 1.5515x over previous
#include <cuda_runtime.h>
#include <cstdint>

#define BIGF 100000000.0f
// 1/(gamma*ln2) with gamma = 0.1, and gamma*ln2
#define INV_G_LN2 14.426950408889634f
#define G_LN2 0.06931471805599453f

__device__ __forceinline__ float fast_ex2(float x) {
    float y; asm("ex2.approx.ftz.f32 %0, %1;" : "=f"(y) : "f"(x)); return y;
}
__device__ __forceinline__ float fast_lg2(float x) {
    float y; asm("lg2.approx.ftz.f32 %0, %1;" : "=f"(y) : "f"(x)); return y;
}
__device__ __forceinline__ float to_tf32(float x) {
    uint32_t y; asm("cvt.rna.tf32.f32 %0, %1;" : "=r"(y) : "f"(x));
    return __uint_as_float(y);
}
__device__ __forceinline__ void mma_tf32(float* d, const float* a, const float* b) {
    asm volatile(
        "mma.sync.aligned.m16n8k8.row.col.f32.tf32.tf32.f32 "
        "{%0,%1,%2,%3}, {%4,%5,%6,%7}, {%8,%9}, {%0,%1,%2,%3};\n"
        : "+f"(d[0]), "+f"(d[1]), "+f"(d[2]), "+f"(d[3])
        : "r"(__float_as_uint(a[0])), "r"(__float_as_uint(a[1])),
          "r"(__float_as_uint(a[2])), "r"(__float_as_uint(a[3])),
          "r"(__float_as_uint(b[0])), "r"(__float_as_uint(b[1])));
}

// Scratch (static device allocations; no cudaMalloc anywhere)
__device__ float g_D[50331648];  // 192 * 512 * 512 floats = 201 MB
__device__ float g_xn[32768];    // 64*512 row norms of x
__device__ float g_yn[32768];    // 64*512 row norms of y
__device__ float g_dtw[192];     // per-(matrix,batch) soft-DTW values

// ---------------------------------------------------------------------------
// Kernel 1: row squared-norms, one warp per row, both tensors at once.
// ---------------------------------------------------------------------------
__global__ void norms_kernel(const float* __restrict__ x, const float* __restrict__ y) {
    int gw = (blockIdx.x * blockDim.x + threadIdx.x) >> 5;
    int lane = threadIdx.x & 31;
    if (gw >= 32768) return;
    const float* p = x + (size_t)gw * 256;
    const float* q = y + (size_t)gw * 256;
    float vx = 0.f, vy = 0.f;
#pragma unroll
    for (int u = 0; u < 8; ++u) {
        float a = p[lane + 32 * u]; vx += a * a;
        float b = q[lane + 32 * u]; vy += b * b;
    }
#pragma unroll
    for (int o = 16; o; o >>= 1) {
        vx += __shfl_xor_sync(0xffffffffu, vx, o);
        vy += __shfl_xor_sync(0xffffffffu, vy, o);
    }
    if (lane == 0) { g_xn[gw] = vx; g_yn[gw] = vy; }
}

// ---------------------------------------------------------------------------
// Kernel 2: squared-distance matrices via tf32 mma.sync tensor cores.
// D[z][i][j] = |A_i|^2 + |B_j|^2 - 2 A_i.B_j, z = m*64+b.
// CTA tile 128x128, BK=16, 256 threads = 8 warps (2x4), warp tile 64x32,
// m16n8k8 fragments 4x4 per warp. Inputs cvt to tf32 at staging time.
// ---------------------------------------------------------------------------
__global__ __launch_bounds__(256, 2) void sqdist_kernel(const float* __restrict__ x,
                                                        const float* __restrict__ y) {
    // pad 136: 136 mod 32 = 8 -> fragment reads (bank = 8*tg + gid) conflict-free
    __shared__ float As[16][136];
    __shared__ float Bs[16][136];

    int z = blockIdx.z;
    int m = z >> 6, b = z & 63;
    const float* A; const float* Bm; const float* an; const float* bn;
    if (m == 0)      { A = x; Bm = y; an = g_xn; bn = g_yn; }
    else if (m == 1) { A = x; Bm = x; an = g_xn; bn = g_xn; }
    else             { A = y; Bm = y; an = g_yn; bn = g_yn; }
    size_t boff = (size_t)b * 512 * 256;
    A += boff; Bm += boff; an += b * 512; bn += b * 512;
    float* C = g_D + (size_t)z * 262144;

    int tid = threadIdx.x;
    int warp = tid >> 5, lane = tid & 31;
    int wm = warp >> 2, wn = warp & 3;          // 2 x 4 warp grid
    int gid = lane >> 2, tg = lane & 3;
    int rowBase = blockIdx.y * 128, colBase = blockIdx.x * 128;
    int warpRow = wm * 64, warpCol = wn * 32;

    float acc[4][4][4];
#pragma unroll
    for (int mt = 0; mt < 4; ++mt)
#pragma unroll
        for (int nt = 0; nt < 4; ++nt)
#pragma unroll
            for (int r = 0; r < 4; ++r) acc[mt][nt][r] = 0.f;

    int ldRow = tid >> 2;          // 0..63
    int ldC4  = tid & 3;           // 0..3 -> k-cols [4*ldC4, 4*ldC4+3]

    for (int kb = 0; kb < 256; kb += 16) {
#pragma unroll
        for (int h = 0; h < 2; ++h) {
            int row = ldRow + h * 64;
            float4 av = *(const float4*)(A  + (size_t)(rowBase + row) * 256 + kb + ldC4 * 4);
            float4 bv = *(const float4*)(Bm + (size_t)(colBase + row) * 256 + kb + ldC4 * 4);
            As[ldC4 * 4 + 0][row] = to_tf32(av.x);
            As[ldC4 * 4 + 1][row] = to_tf32(av.y);
            As[ldC4 * 4 + 2][row] = to_tf32(av.z);
            As[ldC4 * 4 + 3][row] = to_tf32(av.w);
            Bs[ldC4 * 4 + 0][row] = to_tf32(bv.x);
            Bs[ldC4 * 4 + 1][row] = to_tf32(bv.y);
            Bs[ldC4 * 4 + 2][row] = to_tf32(bv.z);
            Bs[ldC4 * 4 + 3][row] = to_tf32(bv.w);
        }
        __syncthreads();
#pragma unroll
        for (int ks = 0; ks < 2; ++ks) {
            int kk = ks * 8;
            float a[4][4];
#pragma unroll
            for (int mt = 0; mt < 4; ++mt) {
                int r0 = warpRow + mt * 16;
                a[mt][0] = As[kk + tg    ][r0 + gid];
                a[mt][1] = As[kk + tg    ][r0 + gid + 8];
                a[mt][2] = As[kk + tg + 4][r0 + gid];
                a[mt][3] = As[kk + tg + 4][r0 + gid + 8];
            }
            float bfrag[4][2];
#pragma unroll
            for (int nt = 0; nt < 4; ++nt) {
                int c0 = warpCol + nt * 8;
                bfrag[nt][0] = Bs[kk + tg    ][c0 + gid];
                bfrag[nt][1] = Bs[kk + tg + 4][c0 + gid];
            }
#pragma unroll
            for (int mt = 0; mt < 4; ++mt)
#pragma unroll
                for (int nt = 0; nt < 4; ++nt)
                    mma_tf32(acc[mt][nt], a[mt], bfrag[nt]);
        }
        __syncthreads();
    }

    // epilogue: D = xn + yn - 2*dot
#pragma unroll
    for (int mt = 0; mt < 4; ++mt) {
        int r = rowBase + warpRow + mt * 16 + gid;
        float an0 = an[r], an1 = an[r + 8];
#pragma unroll
        for (int nt = 0; nt < 4; ++nt) {
            int c = colBase + warpCol + nt * 8 + 2 * tg;
            float bn0 = bn[c], bn1 = bn[c + 1];
            float2 v0, v1;
            v0.x = an0 + bn0 - 2.f * acc[mt][nt][0];
            v0.y = an0 + bn1 - 2.f * acc[mt][nt][1];
            v1.x = an1 + bn0 - 2.f * acc[mt][nt][2];
            v1.y = an1 + bn1 - 2.f * acc[mt][nt][3];
            *(float2*)&C[(size_t)r * 512 + c]       = v0;
            *(float2*)&C[(size_t)(r + 8) * 512 + c] = v1;
        }
    }
}

// ---------------------------------------------------------------------------
// Kernel 3: soft-DTW anti-diagonal DP (unchanged from the passing R5 kernel).
// ---------------------------------------------------------------------------
__global__ __launch_bounds__(512, 2) void dtw_kernel() {
    __shared__ float band[512][17];
    __shared__ float e1[2][16];
    __shared__ float e2[2][16];

    int inst = blockIdx.x;
    const float* __restrict__ D = g_D + (size_t)inst * 262144;
    int t = threadIdx.x;
    int lane = t & 31, warp = t >> 5;

    if (t < 16) { e1[0][t] = BIGF; e1[1][t] = BIGF; e2[0][t] = BIGF; e2[1][t] = BIGF; }
    float r1 = BIGF, r2 = BIGF;
    __syncthreads();

    for (int kb = 2; kb <= 1024; kb += 16) {
        {
            int rbase = warp * 32;
#pragma unroll
            for (int it = 0; it < 16; ++it) {
                int row = rbase + it * 2 + (lane >> 4);
                int u = lane & 15;
                int c = kb - row - 2 + u;
                float v = 0.f;
                if ((unsigned)c < 512u) v = __ldg(&D[row * 512 + c]);
                band[row][u] = v;
            }
        }
        __syncthreads();

        int kend = (kb + 16 > 1025) ? 1025 : (kb + 16);
        for (int k = kb; k < kend; ++k) {
            float up1 = __shfl_up_sync(0xffffffffu, r1, 1);
            float up2 = __shfl_up_sync(0xffffffffu, r2, 1);
            if (lane == 0) {
                if (warp == 0) { up1 = BIGF; up2 = (k == 2) ? 0.f : BIGF; }
                else {
                    int rb = (k + 1) & 1;
                    up1 = e1[rb][warp - 1];
                    up2 = e2[rb][warp - 1];
                }
            }
            int jm1 = k - t - 2;
            bool valid = ((unsigned)jm1 < 512u);
            float d = band[t][k - kb];
            float mn = fminf(fminf(up1, up2), r1);
            float s = fast_ex2((mn - up1) * INV_G_LN2)
                    + fast_ex2((mn - up2) * INV_G_LN2)
                    + fast_ex2((mn - r1)  * INV_G_LN2);
            float sm = mn - G_LN2 * fast_lg2(s);
            r2 = r1;
            r1 = valid ? d + sm : BIGF;
            if (lane == 31) {
                int wb = k & 1;
                e1[wb][warp] = r1;
                e2[wb][warp] = r2;
            }
            __syncthreads();
        }
    }
    if (t == 511) g_dtw[inst] = r1;
}

// ---------------------------------------------------------------------------
// Kernel 4: out[b] = dtw_xy - 0.5*(dtw_xx + dtw_yy)
// ---------------------------------------------------------------------------
__global__ void combine_kernel(float* __restrict__ out) {
    int b = threadIdx.x;
    if (b < 64) out[b] = g_dtw[b] - 0.5f * (g_dtw[64 + b] + g_dtw[128 + b]);
}

extern "C" void kernel_launch(void* const* d_in, const int* in_sizes, int n_in,
                              void* d_out, int out_size) {
    const float* x = (const float*)d_in[0];
    const float* y = (const float*)d_in[1];
    float* out = (float*)d_out;

    norms_kernel<<<4096, 256>>>(x, y);
    dim3 g(4, 4, 192);
    sqdist_kernel<<<g, 256>>>(x, y);
    dtw_kernel<<<192, 512>>>();
    combine_kernel<<<1, 64>>>(out);
}

// round 11
// speedup vs baseline: 2.2945x; 1.4789x over previous
#include <cuda_runtime.h>
#include <cuda_bf16.h>
#include <cstdint>

#define BIGF 100000000.0f
// 1/(gamma*ln2) with gamma = 0.1, and gamma*ln2
#define INV_G_LN2 14.426950408889634f
#define G_LN2 0.06931471805599453f

__device__ __forceinline__ float fast_ex2(float x) {
    float y; asm("ex2.approx.ftz.f32 %0, %1;" : "=f"(y) : "f"(x)); return y;
}
__device__ __forceinline__ float fast_lg2(float x) {
    float y; asm("lg2.approx.ftz.f32 %0, %1;" : "=f"(y) : "f"(x)); return y;
}
__device__ __forceinline__ uint32_t smem_u32(const void* p) {
    uint32_t a;
    asm("{ .reg .u64 t; cvta.to.shared.u64 t, %1; cvt.u32.u64 %0, t; }" : "=r"(a) : "l"(p));
    return a;
}
__device__ __forceinline__ void cp16(uint32_t dst, const void* src) {
    asm volatile("cp.async.cg.shared.global [%0], [%1], 16;" :: "r"(dst), "l"(src) : "memory");
}
__device__ __forceinline__ void ldsm_x4(uint32_t* r, uint32_t addr) {
    asm volatile("ldmatrix.sync.aligned.m8n8.x4.shared.b16 {%0,%1,%2,%3}, [%4];"
                 : "=r"(r[0]), "=r"(r[1]), "=r"(r[2]), "=r"(r[3]) : "r"(addr));
}
__device__ __forceinline__ void mma_bf16(float* d, const uint32_t* a, uint32_t b0, uint32_t b1) {
    asm volatile(
        "mma.sync.aligned.m16n8k16.row.col.f32.bf16.bf16.f32 "
        "{%0,%1,%2,%3}, {%4,%5,%6,%7}, {%8,%9}, {%0,%1,%2,%3};\n"
        : "+f"(d[0]), "+f"(d[1]), "+f"(d[2]), "+f"(d[3])
        : "r"(a[0]), "r"(a[1]), "r"(a[2]), "r"(a[3]), "r"(b0), "r"(b1));
}
// swizzle for 64-byte rows: XOR chunk bits [5:4] with row bits (off bits [8:7])
__device__ __forceinline__ uint32_t swz(uint32_t off) { return off ^ ((off >> 3) & 0x30); }

// Scratch (static device allocations; no cudaMalloc anywhere)
__device__ float g_D[50331648];            // 192 * 512 * 512
__device__ __nv_bfloat16 g_xb[8388608];    // bf16 copy of x
__device__ __nv_bfloat16 g_yb[8388608];    // bf16 copy of y
__device__ float g_xn[32768];
__device__ float g_yn[32768];
__device__ float g_dtw[192];

// ---------------------------------------------------------------------------
// Kernel 1: bf16 conversion + row squared-norms (norms computed FROM the
// rounded bf16 values so D[i][i] ~ 0 and D = exact sqdist of quantized inputs).
// ---------------------------------------------------------------------------
__global__ void norms_kernel(const float* __restrict__ x, const float* __restrict__ y) {
    int gw = (blockIdx.x * blockDim.x + threadIdx.x) >> 5;
    int lane = threadIdx.x & 31;
    if (gw >= 32768) return;
    const float* p = x + (size_t)gw * 256;
    const float* q = y + (size_t)gw * 256;
    float vx = 0.f, vy = 0.f;
#pragma unroll
    for (int u = 0; u < 8; ++u) {
        float a = p[lane + 32 * u];
        float b = q[lane + 32 * u];
        __nv_bfloat16 ab = __float2bfloat16(a);
        __nv_bfloat16 bb = __float2bfloat16(b);
        g_xb[(size_t)gw * 256 + lane + 32 * u] = ab;
        g_yb[(size_t)gw * 256 + lane + 32 * u] = bb;
        float af = __bfloat162float(ab), bf = __bfloat162float(bb);
        vx += af * af;
        vy += bf * bf;
    }
#pragma unroll
    for (int o = 16; o; o >>= 1) {
        vx += __shfl_xor_sync(0xffffffffu, vx, o);
        vy += __shfl_xor_sync(0xffffffffu, vy, o);
    }
    if (lane == 0) { g_xn[gw] = vx; g_yn[gw] = vy; }
}

// ---------------------------------------------------------------------------
// Kernel 2: sqdist via bf16 mma.sync m16n8k16 + ldmatrix + cp.async pipeline.
// CTA 128x128 tile, BK=32 bf16, 256 threads = 8 warps (2x4), warp 64x32.
// Smem rows: 32 bf16 = 64 B, swizzled; double buffered.
// ---------------------------------------------------------------------------
__global__ __launch_bounds__(256, 2) void sqdist_kernel() {
    // [buf][A/B]: A at 0, B at +16384; each buffer 8192 B
    __shared__ __align__(16) uint8_t smem[32768];

    int z = blockIdx.z;
    int m = z >> 6, b = z & 63;
    const __nv_bfloat16* A; const __nv_bfloat16* Bm; const float* an; const float* bn;
    if (m == 0)      { A = g_xb; Bm = g_yb; an = g_xn; bn = g_yn; }
    else if (m == 1) { A = g_xb; Bm = g_xb; an = g_xn; bn = g_xn; }
    else             { A = g_yb; Bm = g_yb; an = g_yn; bn = g_yn; }
    size_t boff = (size_t)b * 512 * 256;
    A += boff; Bm += boff; an += b * 512; bn += b * 512;
    float* C = g_D + (size_t)z * 262144;

    int tid = threadIdx.x, warp = tid >> 5, lane = tid & 31;
    int wm = warp >> 2, wn = warp & 3;
    int gid = lane >> 2, tg = lane & 3;
    int rowBase = blockIdx.y * 128, colBase = blockIdx.x * 128;
    int warpRow = wm * 64, warpCol = wn * 32;

    uint32_t sbase = smem_u32(smem);

    float acc[4][4][4];
#pragma unroll
    for (int mt = 0; mt < 4; ++mt)
#pragma unroll
        for (int nt = 0; nt < 4; ++nt)
#pragma unroll
            for (int r = 0; r < 4; ++r) acc[mt][nt][r] = 0.f;

    // staging: thread -> rows {tid>>2, +64}, 16B chunk tid&3
    int str = tid >> 2, stc = tid & 3;

#define STAGE(buf, it)                                                          \
    {                                                                           \
        int kb = (it) * 32;                                                     \
        _Pragma("unroll")                                                       \
        for (int h = 0; h < 2; ++h) {                                           \
            int r = str + 64 * h;                                               \
            uint32_t off = swz((uint32_t)(r * 64 + stc * 16));                  \
            cp16(sbase + (buf) * 8192 + off,                                    \
                 A + (size_t)(rowBase + r) * 256 + kb + stc * 8);               \
            cp16(sbase + 16384 + (buf) * 8192 + off,                            \
                 Bm + (size_t)(colBase + r) * 256 + kb + stc * 8);              \
        }                                                                       \
        asm volatile("cp.async.commit_group;" ::: "memory");                    \
    }

    STAGE(0, 0);

    for (int it = 0; it < 8; ++it) {
        if (it < 7) {
            STAGE((it + 1) & 1, it + 1);
            asm volatile("cp.async.wait_group 1;" ::: "memory");
        } else {
            asm volatile("cp.async.wait_group 0;" ::: "memory");
        }
        __syncthreads();

        uint32_t sA = sbase + (it & 1) * 8192;
        uint32_t sB = sbase + 16384 + (it & 1) * 8192;
#pragma unroll
        for (int ks = 0; ks < 2; ++ks) {
            uint32_t af[4][4];
#pragma unroll
            for (int mt = 0; mt < 4; ++mt) {
                int rowb = warpRow + mt * 16 + (lane & 15);
                ldsm_x4(af[mt], sA + swz((uint32_t)(rowb * 64 + ks * 32 + (lane >> 4) * 16)));
            }
            uint32_t bf[2][4];
#pragma unroll
            for (int nh = 0; nh < 2; ++nh) {
                int rowb = warpCol + nh * 16 + (lane & 15);
                ldsm_x4(bf[nh], sB + swz((uint32_t)(rowb * 64 + ks * 32 + (lane >> 4) * 16)));
            }
#pragma unroll
            for (int mt = 0; mt < 4; ++mt)
#pragma unroll
                for (int nt = 0; nt < 4; ++nt) {
                    int nh = nt >> 1, w = nt & 1;
                    mma_bf16(acc[mt][nt], af[mt], bf[nh][w], bf[nh][2 + w]);
                }
        }
        __syncthreads();
    }

    // epilogue: D = xn + yn - 2*dot
#pragma unroll
    for (int mt = 0; mt < 4; ++mt) {
        int r = rowBase + warpRow + mt * 16 + gid;
        float an0 = an[r], an1 = an[r + 8];
#pragma unroll
        for (int nt = 0; nt < 4; ++nt) {
            int c = colBase + warpCol + nt * 8 + 2 * tg;
            float bn0 = bn[c], bn1 = bn[c + 1];
            float2 v0, v1;
            v0.x = an0 + bn0 - 2.f * acc[mt][nt][0];
            v0.y = an0 + bn1 - 2.f * acc[mt][nt][1];
            v1.x = an1 + bn0 - 2.f * acc[mt][nt][2];
            v1.y = an1 + bn1 - 2.f * acc[mt][nt][3];
            *(float2*)&C[(size_t)r * 512 + c]       = v0;
            *(float2*)&C[(size_t)(r + 8) * 512 + c] = v1;
        }
    }
#undef STAGE
}

// ---------------------------------------------------------------------------
// Kernel 3: soft-DTW anti-diagonal DP (unchanged, verified).
// ---------------------------------------------------------------------------
__global__ __launch_bounds__(512, 2) void dtw_kernel() {
    __shared__ float band[512][17];
    __shared__ float e1[2][16];
    __shared__ float e2[2][16];

    int inst = blockIdx.x;
    const float* __restrict__ D = g_D + (size_t)inst * 262144;
    int t = threadIdx.x;
    int lane = t & 31, warp = t >> 5;

    if (t < 16) { e1[0][t] = BIGF; e1[1][t] = BIGF; e2[0][t] = BIGF; e2[1][t] = BIGF; }
    float r1 = BIGF, r2 = BIGF;
    __syncthreads();

    for (int kb = 2; kb <= 1024; kb += 16) {
        {
            int rbase = warp * 32;
#pragma unroll
            for (int it = 0; it < 16; ++it) {
                int row = rbase + it * 2 + (lane >> 4);
                int u = lane & 15;
                int c = kb - row - 2 + u;
                float v = 0.f;
                if ((unsigned)c < 512u) v = __ldg(&D[row * 512 + c]);
                band[row][u] = v;
            }
        }
        __syncthreads();

        int kend = (kb + 16 > 1025) ? 1025 : (kb + 16);
        for (int k = kb; k < kend; ++k) {
            float up1 = __shfl_up_sync(0xffffffffu, r1, 1);
            float up2 = __shfl_up_sync(0xffffffffu, r2, 1);
            if (lane == 0) {
                if (warp == 0) { up1 = BIGF; up2 = (k == 2) ? 0.f : BIGF; }
                else {
                    int rb = (k + 1) & 1;
                    up1 = e1[rb][warp - 1];
                    up2 = e2[rb][warp - 1];
                }
            }
            int jm1 = k - t - 2;
            bool valid = ((unsigned)jm1 < 512u);
            float d = band[t][k - kb];
            float mn = fminf(fminf(up1, up2), r1);
            float s = fast_ex2((mn - up1) * INV_G_LN2)
                    + fast_ex2((mn - up2) * INV_G_LN2)
                    + fast_ex2((mn - r1)  * INV_G_LN2);
            float sm = mn - G_LN2 * fast_lg2(s);
            r2 = r1;
            r1 = valid ? d + sm : BIGF;
            if (lane == 31) {
                int wb = k & 1;
                e1[wb][warp] = r1;
                e2[wb][warp] = r2;
            }
            __syncthreads();
        }
    }
    if (t == 511) g_dtw[inst] = r1;
}

// ---------------------------------------------------------------------------
// Kernel 4: out[b] = dtw_xy - 0.5*(dtw_xx + dtw_yy)
// ---------------------------------------------------------------------------
__global__ void combine_kernel(float* __restrict__ out) {
    int b = threadIdx.x;
    if (b < 64) out[b] = g_dtw[b] - 0.5f * (g_dtw[64 + b] + g_dtw[128 + b]);
}

extern "C" void kernel_launch(void* const* d_in, const int* in_sizes, int n_in,
                              void* d_out, int out_size) {
    const float* x = (const float*)d_in[0];
    const float* y = (const float*)d_in[1];
    float* out = (float*)d_out;

    norms_kernel<<<4096, 256>>>(x, y);
    dim3 g(4, 4, 192);
    sqdist_kernel<<<g, 256>>>();
    dtw_kernel<<<192, 512>>>();
    combine_kernel<<<1, 64>>>(out);
}

// round 15
// speedup vs baseline: 2.3572x; 1.0273x over previous
#include <cuda_runtime.h>
#include <cuda_bf16.h>
#include <cuda_fp16.h>
#include <cstdint>

#define BIGF 100000000.0f
// 1/(gamma*ln2) with gamma = 0.1, and gamma*ln2
#define INV_G_LN2 14.426950408889634f
#define G_LN2 0.06931471805599453f

__device__ __forceinline__ float fast_ex2(float x) {
    float y; asm("ex2.approx.ftz.f32 %0, %1;" : "=f"(y) : "f"(x)); return y;
}
__device__ __forceinline__ float fast_lg2(float x) {
    float y; asm("lg2.approx.ftz.f32 %0, %1;" : "=f"(y) : "f"(x)); return y;
}
__device__ __forceinline__ uint32_t smem_u32(const void* p) {
    uint32_t a;
    asm("{ .reg .u64 t; cvta.to.shared.u64 t, %1; cvt.u32.u64 %0, t; }" : "=r"(a) : "l"(p));
    return a;
}
__device__ __forceinline__ void cp16(uint32_t dst, const void* src) {
    asm volatile("cp.async.cg.shared.global [%0], [%1], 16;" :: "r"(dst), "l"(src) : "memory");
}
__device__ __forceinline__ void ldsm_x4(uint32_t* r, uint32_t addr) {
    asm volatile("ldmatrix.sync.aligned.m8n8.x4.shared.b16 {%0,%1,%2,%3}, [%4];"
                 : "=r"(r[0]), "=r"(r[1]), "=r"(r[2]), "=r"(r[3]) : "r"(addr));
}
__device__ __forceinline__ void mma_bf16(float* d, const uint32_t* a, uint32_t b0, uint32_t b1) {
    asm volatile(
        "mma.sync.aligned.m16n8k16.row.col.f32.bf16.bf16.f32 "
        "{%0,%1,%2,%3}, {%4,%5,%6,%7}, {%8,%9}, {%0,%1,%2,%3};\n"
        : "+f"(d[0]), "+f"(d[1]), "+f"(d[2]), "+f"(d[3])
        : "r"(a[0]), "r"(a[1]), "r"(a[2]), "r"(a[3]), "r"(b0), "r"(b1));
}
// swizzle for 64-byte rows: XOR chunk bits [5:4] with row bits (off bits [8:7])
__device__ __forceinline__ uint32_t swz(uint32_t off) { return off ^ ((off >> 3) & 0x30); }

// Scratch (static device allocations; no cudaMalloc anywhere)
__device__ __half g_D[50331648];           // 192 * 512 * 512, fp16 (halves traffic)
__device__ __nv_bfloat16 g_xb[8388608];    // bf16 copy of x
__device__ __nv_bfloat16 g_yb[8388608];    // bf16 copy of y
__device__ float g_xn[32768];
__device__ float g_yn[32768];
__device__ float g_dtw[192];

// ---------------------------------------------------------------------------
// Kernel 1: bf16 conversion + row squared-norms (norms computed FROM the
// rounded bf16 values so D = exact sqdist of the quantized inputs).
// ---------------------------------------------------------------------------
__global__ void norms_kernel(const float* __restrict__ x, const float* __restrict__ y) {
    int gw = (blockIdx.x * blockDim.x + threadIdx.x) >> 5;
    int lane = threadIdx.x & 31;
    if (gw >= 32768) return;
    const float* p = x + (size_t)gw * 256;
    const float* q = y + (size_t)gw * 256;
    float vx = 0.f, vy = 0.f;
#pragma unroll
    for (int u = 0; u < 8; ++u) {
        float a = p[lane + 32 * u];
        float b = q[lane + 32 * u];
        __nv_bfloat16 ab = __float2bfloat16(a);
        __nv_bfloat16 bb = __float2bfloat16(b);
        g_xb[(size_t)gw * 256 + lane + 32 * u] = ab;
        g_yb[(size_t)gw * 256 + lane + 32 * u] = bb;
        float af = __bfloat162float(ab), bf = __bfloat162float(bb);
        vx += af * af;
        vy += bf * bf;
    }
#pragma unroll
    for (int o = 16; o; o >>= 1) {
        vx += __shfl_xor_sync(0xffffffffu, vx, o);
        vy += __shfl_xor_sync(0xffffffffu, vy, o);
    }
    if (lane == 0) { g_xn[gw] = vx; g_yn[gw] = vy; }
}

// ---------------------------------------------------------------------------
// Kernel 2: sqdist via bf16 mma.sync m16n8k16 + ldmatrix + 3-stage cp.async
// pipeline (ONE __syncthreads per k-iteration). CTA 128x128, BK=32, 256 thr,
// 8 warps (2x4), warp tile 64x32. D stored as fp16.
// ---------------------------------------------------------------------------
__global__ __launch_bounds__(256, 2) void sqdist_kernel() {
    // 3 stages x (A 8192 B + B 8192 B) = 49152 B
    __shared__ __align__(16) uint8_t smem[49152];

    int z = blockIdx.z;
    int m = z >> 6, b = z & 63;
    const __nv_bfloat16* A; const __nv_bfloat16* Bm; const float* an; const float* bn;
    if (m == 0)      { A = g_xb; Bm = g_yb; an = g_xn; bn = g_yn; }
    else if (m == 1) { A = g_xb; Bm = g_xb; an = g_xn; bn = g_xn; }
    else             { A = g_yb; Bm = g_yb; an = g_yn; bn = g_yn; }
    size_t boff = (size_t)b * 512 * 256;
    A += boff; Bm += boff; an += b * 512; bn += b * 512;
    __half* C = g_D + (size_t)z * 262144;

    int tid = threadIdx.x, warp = tid >> 5, lane = tid & 31;
    int wm = warp >> 2, wn = warp & 3;
    int gid = lane >> 2, tg = lane & 3;
    int rowBase = blockIdx.y * 128, colBase = blockIdx.x * 128;
    int warpRow = wm * 64, warpCol = wn * 32;

    uint32_t sbase = smem_u32(smem);

    float acc[4][4][4];
#pragma unroll
    for (int mt = 0; mt < 4; ++mt)
#pragma unroll
        for (int nt = 0; nt < 4; ++nt)
#pragma unroll
            for (int r = 0; r < 4; ++r) acc[mt][nt][r] = 0.f;

    // staging: thread -> rows {tid>>2, +64}, 16B chunk tid&3
    int str = tid >> 2, stc = tid & 3;

#define STAGE(buf, it)                                                          \
    {                                                                           \
        int kb = (it) * 32;                                                     \
        _Pragma("unroll")                                                       \
        for (int h = 0; h < 2; ++h) {                                           \
            int r = str + 64 * h;                                               \
            uint32_t off = swz((uint32_t)(r * 64 + stc * 16));                  \
            cp16(sbase + (buf) * 16384 + off,                                   \
                 A + (size_t)(rowBase + r) * 256 + kb + stc * 8);               \
            cp16(sbase + (buf) * 16384 + 8192 + off,                            \
                 Bm + (size_t)(colBase + r) * 256 + kb + stc * 8);              \
        }                                                                       \
        asm volatile("cp.async.commit_group;" ::: "memory");                    \
    }

    STAGE(0, 0);
    STAGE(1, 1);

    for (int it = 0; it < 8; ++it) {
        if (it == 7) asm volatile("cp.async.wait_group 0;" ::: "memory");
        else         asm volatile("cp.async.wait_group 1;" ::: "memory");
        __syncthreads();

        int buf = it % 3;
        uint32_t sA = sbase + buf * 16384;
        uint32_t sB = sA + 8192;
#pragma unroll
        for (int ks = 0; ks < 2; ++ks) {
            uint32_t af[4][4];
#pragma unroll
            for (int mt = 0; mt < 4; ++mt) {
                int rowb = warpRow + mt * 16 + (lane & 15);
                ldsm_x4(af[mt], sA + swz((uint32_t)(rowb * 64 + ks * 32 + (lane >> 4) * 16)));
            }
            uint32_t bf[2][4];
#pragma unroll
            for (int nh = 0; nh < 2; ++nh) {
                int rowb = warpCol + nh * 16 + (lane & 15);
                ldsm_x4(bf[nh], sB + swz((uint32_t)(rowb * 64 + ks * 32 + (lane >> 4) * 16)));
            }
#pragma unroll
            for (int mt = 0; mt < 4; ++mt)
#pragma unroll
                for (int nt = 0; nt < 4; ++nt) {
                    int nh = nt >> 1, w = nt & 1;
                    mma_bf16(acc[mt][nt], af[mt], bf[nh][w], bf[nh][2 + w]);
                }
        }
        if (it < 6) STAGE((it + 2) % 3, it + 2);
    }

    // epilogue: D = xn + yn - 2*dot, stored fp16
#pragma unroll
    for (int mt = 0; mt < 4; ++mt) {
        int r = rowBase + warpRow + mt * 16 + gid;
        float an0 = an[r], an1 = an[r + 8];
#pragma unroll
        for (int nt = 0; nt < 4; ++nt) {
            int c = colBase + warpCol + nt * 8 + 2 * tg;
            float bn0 = bn[c], bn1 = bn[c + 1];
            __half2 v0 = __floats2half2_rn(an0 + bn0 - 2.f * acc[mt][nt][0],
                                           an0 + bn1 - 2.f * acc[mt][nt][1]);
            __half2 v1 = __floats2half2_rn(an1 + bn0 - 2.f * acc[mt][nt][2],
                                           an1 + bn1 - 2.f * acc[mt][nt][3]);
            *(__half2*)&C[(size_t)r * 512 + c]       = v0;
            *(__half2*)&C[(size_t)(r + 8) * 512 + c] = v1;
        }
    }
#undef STAGE
}

// ---------------------------------------------------------------------------
// Kernel 3: soft-DTW anti-diagonal DP (fp16 D band loads; DP in fp32).
// ---------------------------------------------------------------------------
__global__ __launch_bounds__(512, 2) void dtw_kernel() {
    __shared__ float band[512][17];
    __shared__ float e1[2][16];
    __shared__ float e2[2][16];

    int inst = blockIdx.x;
    const __half* __restrict__ D = g_D + (size_t)inst * 262144;
    int t = threadIdx.x;
    int lane = t & 31, warp = t >> 5;

    if (t < 16) { e1[0][t] = BIGF; e1[1][t] = BIGF; e2[0][t] = BIGF; e2[1][t] = BIGF; }
    float r1 = BIGF, r2 = BIGF;
    __syncthreads();

    for (int kb = 2; kb <= 1024; kb += 16) {
        {
            int rbase = warp * 32;
#pragma unroll
            for (int it = 0; it < 16; ++it) {
                int row = rbase + it * 2 + (lane >> 4);
                int u = lane & 15;
                int c = kb - row - 2 + u;
                float v = 0.f;
                if ((unsigned)c < 512u) v = __half2float(__ldg(&D[row * 512 + c]));
                band[row][u] = v;
            }
        }
        __syncthreads();

        int kend = (kb + 16 > 1025) ? 1025 : (kb + 16);
        for (int k = kb; k < kend; ++k) {
            float up1 = __shfl_up_sync(0xffffffffu, r1, 1);
            float up2 = __shfl_up_sync(0xffffffffu, r2, 1);
            if (lane == 0) {
                if (warp == 0) { up1 = BIGF; up2 = (k == 2) ? 0.f : BIGF; }
                else {
                    int rb = (k + 1) & 1;
                    up1 = e1[rb][warp - 1];
                    up2 = e2[rb][warp - 1];
                }
            }
            int jm1 = k - t - 2;
            bool valid = ((unsigned)jm1 < 512u);
            float d = band[t][k - kb];
            float mn = fminf(fminf(up1, up2), r1);
            float s = fast_ex2((mn - up1) * INV_G_LN2)
                    + fast_ex2((mn - up2) * INV_G_LN2)
                    + fast_ex2((mn - r1)  * INV_G_LN2);
            float sm = mn - G_LN2 * fast_lg2(s);
            r2 = r1;
            r1 = valid ? d + sm : BIGF;
            if (lane == 31) {
                int wb = k & 1;
                e1[wb][warp] = r1;
                e2[wb][warp] = r2;
            }
            __syncthreads();
        }
    }
    if (t == 511) g_dtw[inst] = r1;
}

// ---------------------------------------------------------------------------
// Kernel 4: out[b] = dtw_xy - 0.5*(dtw_xx + dtw_yy)
// ---------------------------------------------------------------------------
__global__ void combine_kernel(float* __restrict__ out) {
    int b = threadIdx.x;
    if (b < 64) out[b] = g_dtw[b] - 0.5f * (g_dtw[64 + b] + g_dtw[128 + b]);
}

extern "C" void kernel_launch(void* const* d_in, const int* in_sizes, int n_in,
                              void* d_out, int out_size) {
    const float* x = (const float*)d_in[0];
    const float* y = (const float*)d_in[1];
    float* out = (float*)d_out;

    norms_kernel<<<4096, 256>>>(x, y);
    dim3 g(4, 4, 192);
    sqdist_kernel<<<g, 256>>>();
    dtw_kernel<<<192, 512>>>();
    combine_kernel<<<1, 64>>>(out);
}